// round 6
// baseline (speedup 1.0000x reference)
#include <cuda_runtime.h>
#include <cuda_bf16.h>

// LeakyAvg: out[b,h,t,d] = sum_{s<=t} exp(-beta_h*(t-s)) * k[b,h,s,d]
// = recurrence y[t] = w*y[t-1] + k[t], w = exp(-beta_h), beta_h in [0.5, 5].
//
// R6 = R5 (block chunked scan, CH=8, float2 lanes, 24-step warm-up) plus
// L2 prefetch of each warp's whole 2KB chunk at kernel entry.
// Rationale: profile shows no pipe >40% -> exposed DRAM latency, not BW.
// prefetch.global.L2 is fire-and-forget (no regs, no scoreboard), so every
// resident warp's working set starts moving DRAM->L2 immediately; the
// real LDGs then complete at L2 latency and the DRAM read pipe saturates.

#define BB 4
#define NH 16
#define TT 2048
#define HS 64
#define EXP_SCALING 10.0f

#define CH 8                   // timesteps per warp-chunk
#define NBODY 16               // body chunks per block
#define NWARM 3                // warm chunks (24-step warm-up)
#define NWARPB (NBODY + NWARM) // 19 warps
#define THREADS (NWARPB * 32)  // 608
#define TILE (NBODY * CH)      // 128 timesteps per block
#define NTILES (TT / TILE)     // 16
#define NROWS (BB * NH)        // 64

__global__ void __launch_bounds__(THREADS, 3) leaky_avg_kernel(
    const float* __restrict__ k,
    const float* __restrict__ beta_param,
    float* __restrict__ out)
{
    const int lane = threadIdx.x & 31;
    const int j    = threadIdx.x >> 5;            // warp index in block (0..18)
    const int row  = blockIdx.x >> 4;             // bh index (0..63)
    const int tile = blockIdx.x & (NTILES - 1);   // 0..15
    const int h    = row & (NH - 1);

    // chunk start: warm chunks (j<NWARM) sit at [tile0-24, tile0)
    const int chunk_start = tile * TILE + (j - NWARM) * CH;

    // This warp's chunk is CH rows x 256B = 2KB contiguous. Prefetch its 16
    // cache lines to L2 before anything else (lanes 0..15, one line each).
    const char* kbyte = reinterpret_cast<const char*>(k)
                      + ((size_t)row * TT + (size_t)chunk_start) * (HS * 4);
    if (chunk_start >= 0 && lane < (CH * HS * 4 / 128)) {
        asm volatile("prefetch.global.L2 [%0];"
                     :: "l"(kbyte + (size_t)lane * 128));
    }

    const float beta = fabsf(beta_param[h]) * EXP_SCALING;
    const float w    = expf(-beta);
    const float w2 = w * w, w4 = w2 * w2;
    const float w8 = w4 * w4;                     // per-chunk decay (CH=8)

    // float2 view of this (b,h) row at this lane's 2 columns
    const float2* __restrict__ kp =
        reinterpret_cast<const float2*>(k + (size_t)row * TT * HS)
        + lane + (size_t)chunk_start * (HS / 2);

    // ---- Phase 1: front-batched loads, local inclusive scan in regs ----
    float2 v[CH];
    if (chunk_start >= 0) {
        #pragma unroll
        for (int u = 0; u < CH; ++u)
            v[u] = kp[(size_t)u * (HS / 2)];
    } else {
        #pragma unroll
        for (int u = 0; u < CH; ++u)
            v[u] = make_float2(0.0f, 0.0f);
        // (only whole-chunk-negative case occurs: warm chunks of tile 0)
    }

    float2 y = make_float2(0.0f, 0.0f);
    #pragma unroll
    for (int u = 0; u < CH; ++u) {
        y.x = fmaf(w, y.x, v[u].x);
        y.y = fmaf(w, y.y, v[u].y);
        v[u] = y;
    }

    __shared__ float2 sS[NWARPB * 32];
    sS[j * 32 + lane] = y;                        // chunk-final state
    __syncthreads();

    // ---- Phase 2+3: body warps fold carry and store corrected outputs ----
    if (j >= NWARM) {
        float2 C = make_float2(0.0f, 0.0f);
        for (int i = 0; i < j; ++i) {             // C = sum_i S_i * w8^(j-1-i)
            const float2 s = sS[i * 32 + lane];
            C.x = fmaf(C.x, w8, s.x);
            C.y = fmaf(C.y, w8, s.y);
        }

        float2* __restrict__ op =
            reinterpret_cast<float2*>(out + (size_t)row * TT * HS)
            + lane + (size_t)chunk_start * (HS / 2);

        float px = C.x * w, py = C.y * w;         // correction C * w^(u+1)
        #pragma unroll
        for (int u = 0; u < CH; ++u) {
            float2 r;
            r.x = v[u].x + px;
            r.y = v[u].y + py;
            __stcs(op + (size_t)u * (HS / 2), r); // evict-first streaming store
            px *= w;
            py *= w;
        }
    }
}

extern "C" void kernel_launch(void* const* d_in, const int* in_sizes, int n_in,
                              void* d_out, int out_size)
{
    const float* k    = (const float*)d_in[0];   // (B, NH, T, HS) f32
    const float* beta = (const float*)d_in[1];   // (1, NH, 1, 1) f32
    float*       out  = (float*)d_out;           // (B, NH, T, HS) f32

    const int blocks = NROWS * NTILES;           // 1024
    leaky_avg_kernel<<<blocks, THREADS>>>(k, beta, out);
}

// round 8
// speedup vs baseline: 1.0350x; 1.0350x over previous
#include <cuda_runtime.h>
#include <cuda_bf16.h>

// LeakyAvg: out[b,h,t,d] = sum_{s<=t} exp(-beta_h*(t-s)) * k[b,h,s,d]
// = recurrence y[t] = w*y[t-1] + k[t], w = exp(-beta_h), beta_h in [0.5, 5].
//
// R7 (resubmit after infra failure): barrier-free software-pipelined scan.
//  - Warp owns BODY=32 timesteps (+WARM=24 halo; truncation e^{-12}~6e-6 rel,
//    validated passing in R5/R6). Lane owns 2 head-dims (float2) -> 256B
//    coalesced per warp access.
//  - 7 groups of 8 timesteps, fully unrolled, double-buffered: group g+1's
//    loads issue BEFORE computing group g => 8 loads always in flight per
//    warp, no phase gaps. Tile-0 negative groups are uniform zero-fills so
//    every warp runs the same schedule.
//  - 4096 warps (64 rows x 64 tiles) = 27.7 warps/SM: whole grid resident,
//    exactly ONE wave, no block-level barrier, no wave tail.

#define BB 4
#define NH 16
#define TT 2048
#define HS 64
#define EXP_SCALING 10.0f

#define BODY 32                 // stored timesteps per warp
#define WARMS 24                // warm-up halo
#define G 8                     // group (pipeline stage) size
#define NG ((BODY + WARMS) / G) // 7 groups
#define WARMG (WARMS / G)       // 3 warm groups

#define NTILES (TT / BODY)      // 64
#define NROWS (BB * NH)         // 64
#define NWARPS (NROWS * NTILES) // 4096
#define TPB 64                  // 2 warps per block
#define NBLK (NWARPS * 32 / TPB)

__global__ void __launch_bounds__(TPB) leaky_avg_kernel(
    const float* __restrict__ k,
    const float* __restrict__ beta_param,
    float* __restrict__ out)
{
    const int gw   = (blockIdx.x * TPB + threadIdx.x) >> 5;  // global warp
    const int lane = threadIdx.x & 31;
    const int tile = gw & (NTILES - 1);
    const int row  = gw >> 6;                                // / NTILES
    const int h    = row & (NH - 1);

    const float w = expf(-fabsf(beta_param[h]) * EXP_SCALING);

    const int t0     = tile * BODY;
    const int startT = t0 - WARMS;     // negative only for tile 0 (groups 0..2)

    const float2* __restrict__ kp =
        reinterpret_cast<const float2*>(k + (size_t)row * TT * HS) + lane;
    float2* __restrict__ op =
        reinterpret_cast<float2*>(out + (size_t)row * TT * HS) + lane;

    float2 buf[2][G];

    // prologue: load group 0
    {
        const int tg = startT;
        if (tg >= 0) {
            #pragma unroll
            for (int u = 0; u < G; ++u)
                buf[0][u] = kp[(size_t)(tg + u) * (HS / 2)];
        } else {
            #pragma unroll
            for (int u = 0; u < G; ++u)
                buf[0][u] = make_float2(0.0f, 0.0f);
        }
    }

    float2 y = make_float2(0.0f, 0.0f);

    #pragma unroll
    for (int g = 0; g < NG; ++g) {
        // issue next group's loads before touching current buffer
        if (g + 1 < NG) {
            const int tg = startT + (g + 1) * G;
            if (tg >= 0) {
                #pragma unroll
                for (int u = 0; u < G; ++u)
                    buf[(g + 1) & 1][u] = kp[(size_t)(tg + u) * (HS / 2)];
            } else {
                #pragma unroll
                for (int u = 0; u < G; ++u)
                    buf[(g + 1) & 1][u] = make_float2(0.0f, 0.0f);
            }
        }

        const float2* b = buf[g & 1];
        if (g < WARMG) {
            // warm-up: scan only
            #pragma unroll
            for (int u = 0; u < G; ++u) {
                y.x = fmaf(w, y.x, b[u].x);
                y.y = fmaf(w, y.y, b[u].y);
            }
        } else {
            // body: scan + store (tg = t0 + (g-WARMG)*G >= 0 always)
            const int tg = startT + g * G;
            #pragma unroll
            for (int u = 0; u < G; ++u) {
                y.x = fmaf(w, y.x, b[u].x);
                y.y = fmaf(w, y.y, b[u].y);
                float2 r; r.x = y.x; r.y = y.y;
                __stcs(op + (size_t)(tg + u) * (HS / 2), r);
            }
        }
    }
}

extern "C" void kernel_launch(void* const* d_in, const int* in_sizes, int n_in,
                              void* d_out, int out_size)
{
    const float* k    = (const float*)d_in[0];   // (B, NH, T, HS) f32
    const float* beta = (const float*)d_in[1];   // (1, NH, 1, 1) f32
    float*       out  = (float*)d_out;           // (B, NH, T, HS) f32

    leaky_avg_kernel<<<NBLK, TPB>>>(k, beta, out);
}